// round 14
// baseline (speedup 1.0000x reference)
#include <cuda_runtime.h>
#include <stdint.h>

#define N_NODES 50000
#define N_EDGES 800000
#define D 64
#define BN_EPS 1e-5f
#define TILE_ROWS 128
#define XS_PITCH (D + 4)
#define GEMM_BLOCKS ((N_NODES + TILE_ROWS - 1) / TILE_ROWS)   // 391
#define SCAN_THREADS 1024
#define SCAN_CHUNK ((N_NODES + SCAN_THREADS - 1) / SCAN_THREADS)  // 49
#define CHAIN 32                       // contiguous sorted edges per half-warp
#define CHUNK (2 * CHAIN)              // edges per warp
#define AGG_WARPS ((N_EDGES + CHUNK - 1) / CHUNK)              // 12500

// Scratch (static device globals — no allocations allowed)
__device__ float g_agg0[N_NODES * D];      // layer-0 neighbor sums
__device__ float g_agg1[N_NODES * D];      // layer-1 neighbor sums
__device__ float g_hpre[N_NODES * D];      // pre-BN GEMM1 output
__device__ float g_stats[2][2 * D];        // per-layer: [0:64) sums, [64:128) sumsq
__device__ int   g_deg   [N_NODES];
__device__ int   g_cursor[N_NODES];
__device__ int   g_esrc  [N_EDGES];        // src, dst-sorted
__device__ int   g_edst  [N_EDGES];        // dst, sorted (runs contiguous)

// ---------------------------------------------------------------------------
// zero agg buffers, BN stats, degree histogram (single upfront launch)
// ---------------------------------------------------------------------------
__global__ void k_zero() {
    int i = blockIdx.x * blockDim.x + threadIdx.x;   // 2*800000 float4s exactly
    const int n4 = N_NODES * D / 4;
    float4 z = make_float4(0.f, 0.f, 0.f, 0.f);
    if (i < n4)          reinterpret_cast<float4*>(g_agg0)[i] = z;
    else if (i < 2 * n4) reinterpret_cast<float4*>(g_agg1)[i - n4] = z;
    if (i < N_NODES / 4)
        reinterpret_cast<int4*>(g_deg)[i] = make_int4(0, 0, 0, 0);
    if (blockIdx.x == 0 && threadIdx.x < 2 * 2 * D)
        (&g_stats[0][0])[threadIdx.x] = 0.0f;
}

// ---------------------------------------------------------------------------
// build: per-dst histogram -> exclusive scan -> stable-ish fill (sorted by dst)
// all 1 edge per thread (latency hidden by parallelism, no serial chains)
// ---------------------------------------------------------------------------
__global__ void k_hist(const int* __restrict__ dst) {
    int e = blockIdx.x * blockDim.x + threadIdx.x;
    if (e < N_EDGES) atomicAdd(&g_deg[dst[e]], 1);
}

__global__ __launch_bounds__(SCAN_THREADS) void k_scan() {
    __shared__ int part[SCAN_THREADS];
    int tid = threadIdx.x;
    int base = tid * SCAN_CHUNK;

    int s = 0;
    #pragma unroll
    for (int i = 0; i < SCAN_CHUNK; i++) {
        int idx = base + i;
        if (idx < N_NODES) s += g_deg[idx];
    }
    part[tid] = s;
    __syncthreads();

    for (int off = 1; off < SCAN_THREADS; off <<= 1) {
        int v = 0;
        if (tid >= off) v = part[tid - off];
        __syncthreads();
        if (tid >= off) part[tid] += v;
        __syncthreads();
    }

    int run = (tid == 0) ? 0 : part[tid - 1];
    #pragma unroll
    for (int i = 0; i < SCAN_CHUNK; i++) {
        int idx = base + i;
        if (idx < N_NODES) {
            g_cursor[idx] = run;
            run += g_deg[idx];
        }
    }
}

__global__ void k_fill(const int* __restrict__ src, const int* __restrict__ dst) {
    int e = blockIdx.x * blockDim.x + threadIdx.x;
    if (e < N_EDGES) {
        int d = dst[e];
        int pos = atomicAdd(&g_cursor[d], 1);
        g_esrc[pos] = src[e];
        g_edst[pos] = d;
    }
}

// ---------------------------------------------------------------------------
// segmented aggregation over dst-sorted edges:
// half-warp (16 lanes, one float4 slice each) owns CHAIN contiguous edges;
// int4 index loads (4 edges per 16B), 4 independent row gathers per group,
// software-pipelined one group ahead; same-dst runs combined in registers,
// flushed with red.global.add.v4 (atomic across chain boundaries).
// ---------------------------------------------------------------------------
__device__ __forceinline__ void redg_v4(float* p, float4 v) {
    size_t a = __cvta_generic_to_global(p);
    asm volatile("red.global.add.v4.f32 [%0], {%1,%2,%3,%4};"
                 :: "l"(a), "f"(v.x), "f"(v.y), "f"(v.z), "f"(v.w)
                 : "memory");
}

#define AGG_STEP(dj, vj) do {                                        \
    if ((dj) == cur_d) {                                             \
        acc.x += (vj).x; acc.y += (vj).y;                            \
        acc.z += (vj).z; acc.w += (vj).w;                            \
    } else {                                                         \
        if (cur_d >= 0) redg_v4(agg + (size_t)cur_d * D + q, acc);   \
        cur_d = (dj); acc = (vj);                                    \
    }                                                                \
} while (0)

__global__ __launch_bounds__(256) void k_agg(
    const float* __restrict__ xin,
    float* __restrict__ agg)
{
    int wg   = (blockIdx.x * blockDim.x + threadIdx.x) >> 5;
    int lane = threadIdx.x & 31;
    int base = wg * CHUNK + (lane >> 4) * CHAIN;
    if (base >= N_EDGES) return;                 // 800000 = 12500*64 exact
    int q = (lane & 15) << 2;                    // float offset: 0,4,...,60

    const int4* dp = reinterpret_cast<const int4*>(g_edst + base);
    const int4* sp = reinterpret_cast<const int4*>(g_esrc + base);

    int4 dd = dp[0];
    int4 ss = sp[0];
    float4 v0 = *reinterpret_cast<const float4*>(xin + (size_t)ss.x * D + q);
    float4 v1 = *reinterpret_cast<const float4*>(xin + (size_t)ss.y * D + q);
    float4 v2 = *reinterpret_cast<const float4*>(xin + (size_t)ss.z * D + q);
    float4 v3 = *reinterpret_cast<const float4*>(xin + (size_t)ss.w * D + q);

    int cur_d = -1;
    float4 acc = make_float4(0.f, 0.f, 0.f, 0.f);

    #pragma unroll 1
    for (int g = 1; g < CHAIN / 4; g++) {
        int4 ddn = dp[g];
        int4 ssn = sp[g];
        float4 w0 = *reinterpret_cast<const float4*>(xin + (size_t)ssn.x * D + q);
        float4 w1 = *reinterpret_cast<const float4*>(xin + (size_t)ssn.y * D + q);
        float4 w2 = *reinterpret_cast<const float4*>(xin + (size_t)ssn.z * D + q);
        float4 w3 = *reinterpret_cast<const float4*>(xin + (size_t)ssn.w * D + q);

        AGG_STEP(dd.x, v0);
        AGG_STEP(dd.y, v1);
        AGG_STEP(dd.z, v2);
        AGG_STEP(dd.w, v3);

        dd = ddn;
        v0 = w0; v1 = w1; v2 = w2; v3 = w3;
    }
    AGG_STEP(dd.x, v0);
    AGG_STEP(dd.y, v1);
    AGG_STEP(dd.z, v2);
    AGG_STEP(dd.w, v3);
    if (cur_d >= 0) redg_v4(agg + (size_t)cur_d * D + q, acc);
}

// ---------------------------------------------------------------------------
// Shared GEMM core: 128-row tile, 256 threads, 8 rows x 4 cols per thread.
// ---------------------------------------------------------------------------
__device__ __forceinline__ void gemm_core(
    const float (*Xs)[XS_PITCH], const float* Ws,
    int tx, int ty, float4 acc[8])
{
    #pragma unroll
    for (int r = 0; r < 8; r++) acc[r] = make_float4(0.f, 0.f, 0.f, 0.f);

    #pragma unroll 4
    for (int k = 0; k < D; k += 4) {
        float4 xr[8];
        #pragma unroll
        for (int r = 0; r < 8; r++)
            xr[r] = *reinterpret_cast<const float4*>(&Xs[ty + 16 * r][k]);
        #pragma unroll
        for (int i = 0; i < 4; i++) {
            float4 w = *reinterpret_cast<const float4*>(&Ws[(k + i) * D + tx * 4]);
            #pragma unroll
            for (int r = 0; r < 8; r++) {
                float xv = (i == 0) ? xr[r].x : (i == 1) ? xr[r].y
                         : (i == 2) ? xr[r].z : xr[r].w;
                acc[r].x = fmaf(xv, w.x, acc[r].x);
                acc[r].y = fmaf(xv, w.y, acc[r].y);
                acc[r].z = fmaf(xv, w.z, acc[r].z);
                acc[r].w = fmaf(xv, w.w, acc[r].w);
            }
        }
    }
}

// ---------------------------------------------------------------------------
// GEMM1: hpre = (agg + x) @ W1 + b1, accumulating BN column sum / sumsq.
// ---------------------------------------------------------------------------
__global__ __launch_bounds__(256) void k_gemm1(
    const float* __restrict__ agg, const float* __restrict__ x,
    const float* __restrict__ W1, const float* __restrict__ b1,
    float* __restrict__ stats)
{
    __shared__ __align__(16) float Ws[D * D];
    __shared__ __align__(16) float Xs[TILE_ROWS][XS_PITCH];
    __shared__ float s_sum[D], s_sq[D];

    int tid = threadIdx.x;
    int row0 = blockIdx.x * TILE_ROWS;

    #pragma unroll
    for (int i = tid; i < D * D / 4; i += 256)
        reinterpret_cast<float4*>(Ws)[i] = reinterpret_cast<const float4*>(W1)[i];
    if (tid < D) { s_sum[tid] = 0.0f; s_sq[tid] = 0.0f; }

    #pragma unroll
    for (int i = tid; i < TILE_ROWS * (D / 4); i += 256) {
        int r  = i >> 4;
        int c4 = (i & 15) << 2;
        int row = row0 + r;
        float4 v = make_float4(0.f, 0.f, 0.f, 0.f);
        if (row < N_NODES) {
            float4 a  = *reinterpret_cast<const float4*>(&agg[(size_t)row * D + c4]);
            float4 xv = *reinterpret_cast<const float4*>(&x  [(size_t)row * D + c4]);
            v.x = a.x + xv.x;  v.y = a.y + xv.y;
            v.z = a.z + xv.z;  v.w = a.w + xv.w;
        }
        *reinterpret_cast<float4*>(&Xs[r][c4]) = v;
    }
    __syncthreads();

    int tx = tid & 15;
    int ty = tid >> 4;

    float4 acc[8];
    gemm_core(Xs, Ws, tx, ty, acc);

    float4 bb = *reinterpret_cast<const float4*>(&b1[tx * 4]);
    float4 csum = make_float4(0.f, 0.f, 0.f, 0.f);
    float4 csq  = make_float4(0.f, 0.f, 0.f, 0.f);

    #pragma unroll
    for (int r = 0; r < 8; r++) {
        int row = row0 + ty + 16 * r;
        if (row < N_NODES) {
            float4 h;
            h.x = acc[r].x + bb.x;
            h.y = acc[r].y + bb.y;
            h.z = acc[r].z + bb.z;
            h.w = acc[r].w + bb.w;
            *reinterpret_cast<float4*>(&g_hpre[(size_t)row * D + tx * 4]) = h;
            csum.x += h.x;  csq.x = fmaf(h.x, h.x, csq.x);
            csum.y += h.y;  csq.y = fmaf(h.y, h.y, csq.y);
            csum.z += h.z;  csq.z = fmaf(h.z, h.z, csq.z);
            csum.w += h.w;  csq.w = fmaf(h.w, h.w, csq.w);
        }
    }
    atomicAdd(&s_sum[tx * 4 + 0], csum.x);
    atomicAdd(&s_sum[tx * 4 + 1], csum.y);
    atomicAdd(&s_sum[tx * 4 + 2], csum.z);
    atomicAdd(&s_sum[tx * 4 + 3], csum.w);
    atomicAdd(&s_sq [tx * 4 + 0], csq.x);
    atomicAdd(&s_sq [tx * 4 + 1], csq.y);
    atomicAdd(&s_sq [tx * 4 + 2], csq.z);
    atomicAdd(&s_sq [tx * 4 + 3], csq.w);
    __syncthreads();

    if (tid < D) {
        atomicAdd(&stats[tid],     s_sum[tid]);
        atomicAdd(&stats[D + tid], s_sq[tid]);
    }
}

// ---------------------------------------------------------------------------
// GEMM2: out = relu( relu(BN(g_hpre)) @ W2 + b2 )
// ---------------------------------------------------------------------------
__global__ __launch_bounds__(256) void k_gemm2(
    const float* __restrict__ W2, const float* __restrict__ b2,
    const float* __restrict__ gam, const float* __restrict__ beta,
    const float* __restrict__ stats,
    float* __restrict__ out)
{
    __shared__ __align__(16) float Ws[D * D];
    __shared__ __align__(16) float Xs[TILE_ROWS][XS_PITCH];
    __shared__ __align__(16) float s_scale[D];
    __shared__ __align__(16) float s_shift[D];

    int tid = threadIdx.x;
    int row0 = blockIdx.x * TILE_ROWS;

    if (tid < D) {
        const float invN = 1.0f / (float)N_NODES;
        float mean = stats[tid] * invN;
        float var  = fmaf(-mean, mean, stats[D + tid] * invN);
        float sc   = gam[tid] * rsqrtf(var + BN_EPS);
        s_scale[tid] = sc;
        s_shift[tid] = beta[tid] - mean * sc;
    }
    #pragma unroll
    for (int i = tid; i < D * D / 4; i += 256)
        reinterpret_cast<float4*>(Ws)[i] = reinterpret_cast<const float4*>(W2)[i];
    __syncthreads();

    #pragma unroll
    for (int i = tid; i < TILE_ROWS * (D / 4); i += 256) {
        int r  = i >> 4;
        int c4 = (i & 15) << 2;
        int row = row0 + r;
        float4 v = make_float4(0.f, 0.f, 0.f, 0.f);
        if (row < N_NODES) {
            float4 hv = *reinterpret_cast<const float4*>(&g_hpre[(size_t)row * D + c4]);
            float4 sc = *reinterpret_cast<const float4*>(&s_scale[c4]);
            float4 sh = *reinterpret_cast<const float4*>(&s_shift[c4]);
            v.x = fmaxf(fmaf(hv.x, sc.x, sh.x), 0.0f);
            v.y = fmaxf(fmaf(hv.y, sc.y, sh.y), 0.0f);
            v.z = fmaxf(fmaf(hv.z, sc.z, sh.z), 0.0f);
            v.w = fmaxf(fmaf(hv.w, sc.w, sh.w), 0.0f);
        }
        *reinterpret_cast<float4*>(&Xs[r][c4]) = v;
    }
    __syncthreads();

    int tx = tid & 15;
    int ty = tid >> 4;

    float4 acc[8];
    gemm_core(Xs, Ws, tx, ty, acc);

    float4 bb = *reinterpret_cast<const float4*>(&b2[tx * 4]);
    #pragma unroll
    for (int r = 0; r < 8; r++) {
        int row = row0 + ty + 16 * r;
        if (row < N_NODES) {
            float4 h;
            h.x = fmaxf(acc[r].x + bb.x, 0.0f);
            h.y = fmaxf(acc[r].y + bb.y, 0.0f);
            h.z = fmaxf(acc[r].z + bb.z, 0.0f);
            h.w = fmaxf(acc[r].w + bb.w, 0.0f);
            *reinterpret_cast<float4*>(&out[(size_t)row * D + tx * 4]) = h;
        }
    }
}

// ---------------------------------------------------------------------------
// launch
// ---------------------------------------------------------------------------
extern "C" void kernel_launch(void* const* d_in, const int* in_sizes, int n_in,
                              void* d_out, int out_size)
{
    const float* x    = (const float*)d_in[0];
    const int*   ei   = (const int*)d_in[1];      // int32 (JAX x64 disabled)
    const float* W1_0 = (const float*)d_in[2];
    const float* b1_0 = (const float*)d_in[3];
    const float* g_0  = (const float*)d_in[4];
    const float* be_0 = (const float*)d_in[5];
    const float* W2_0 = (const float*)d_in[6];
    const float* b2_0 = (const float*)d_in[7];
    const float* W1_1 = (const float*)d_in[8];
    const float* b1_1 = (const float*)d_in[9];
    const float* g_1  = (const float*)d_in[10];
    const float* be_1 = (const float*)d_in[11];
    const float* W2_1 = (const float*)d_in[12];
    const float* b2_1 = (const float*)d_in[13];

    const int* src = ei;              // edge_index[0] = message source
    const int* dst = ei + N_EDGES;    // edge_index[1] = aggregation target

    float* h1 = (float*)d_out;
    float* h2 = h1 + (size_t)N_NODES * D;

    float* a0;  cudaGetSymbolAddress((void**)&a0,  g_agg0);
    float* a1;  cudaGetSymbolAddress((void**)&a1,  g_agg1);
    float* st0; cudaGetSymbolAddress((void**)&st0, g_stats);
    float* st1 = st0 + 2 * D;

    // upfront zero + edge sort-by-dst (shared by both layers)
    k_zero<<<(2 * N_NODES * D / 4 + 255) / 256, 256>>>();
    k_hist<<<(N_EDGES + 255) / 256, 256>>>(dst);
    k_scan<<<1, SCAN_THREADS>>>();
    k_fill<<<(N_EDGES + 255) / 256, 256>>>(src, dst);

    // ---- layer 0 ----
    k_agg  <<<(AGG_WARPS * 32 + 255) / 256, 256>>>(x, a0);
    k_gemm1<<<GEMM_BLOCKS, 256>>>(a0, x, W1_0, b1_0, st0);
    k_gemm2<<<GEMM_BLOCKS, 256>>>(W2_0, b2_0, g_0, be_0, st0, h1);

    // ---- layer 1 ----
    k_agg  <<<(AGG_WARPS * 32 + 255) / 256, 256>>>(h1, a1);
    k_gemm1<<<GEMM_BLOCKS, 256>>>(a1, h1, W1_1, b1_1, st1);
    k_gemm2<<<GEMM_BLOCKS, 256>>>(W2_1, b2_1, g_1, be_1, st1, h2);
}